// round 3
// baseline (speedup 1.0000x reference)
#include <cuda_runtime.h>
#include <math.h>

#define NIN 14
#define NH 256
#define KTOT 10
#define TM 64
#define NTHREADS 256
#define XROW 272   // 256 summary + 14 tower + 2 zero pad

// Padded first-layer weights (rows 270..271 zeroed) so the GEMM k-loop can run
// in uniform chunks of 4 without OOB reads of the 270-row inputs.
__device__ __align__(16) float g_M1w_pad[XROW * NH];
__device__ __align__(16) float g_O1w_pad[XROW * NH];

__global__ void pad_weights_kernel(const float* __restrict__ M1w,
                                   const float* __restrict__ O1w) {
    int idx = blockIdx.x * blockDim.x + threadIdx.x;
    if (idx >= XROW * NH) return;
    int k = idx / NH;           // idx = k*NH + c, matches source [270][256] layout
    float m = 0.f, o = 0.f;
    if (k < 270) { m = M1w[idx]; o = O1w[idx]; }
    g_M1w_pad[idx] = m;
    g_O1w_pad[idx] = o;
}

// out[r][c] = relu( sum_k In[r][k] * W[k][c] + bias[c] ),  64 rows x 256 cols.
// Thread (tr,tc): rows tr*8..+7, cols tc*8..+7. A from SMEM (warp broadcast),
// B from global (identical across the 8 warps -> L1 hits).
template <int KD>
__device__ __forceinline__ void gemm_relu_256(
    const float* __restrict__ In, const int inRow,
    const float* __restrict__ W, const float* __restrict__ bias,
    float* __restrict__ Out, const int outRow, const int tid)
{
    const int tr = tid >> 5;
    const int tc = tid & 31;

    float acc[8][8];
#pragma unroll
    for (int i = 0; i < 8; i++)
#pragma unroll
        for (int j = 0; j < 8; j++) acc[i][j] = 0.f;

    const float* inB = In + tr * 8 * inRow;
    const float* wB  = W + tc * 8;

#pragma unroll 1
    for (int k0 = 0; k0 < KD; k0 += 4) {
        float4 a4[8];
#pragma unroll
        for (int i = 0; i < 8; i++)
            a4[i] = *(const float4*)(inB + i * inRow + k0);

        float4 b0[4], b1[4];
#pragma unroll
        for (int kk = 0; kk < 4; kk++) {
            b0[kk] = *(const float4*)(wB + (k0 + kk) * NH);
            b1[kk] = *(const float4*)(wB + (k0 + kk) * NH + 4);
        }

#pragma unroll
        for (int kk = 0; kk < 4; kk++) {
            float bv[8] = {b0[kk].x, b0[kk].y, b0[kk].z, b0[kk].w,
                           b1[kk].x, b1[kk].y, b1[kk].z, b1[kk].w};
#pragma unroll
            for (int i = 0; i < 8; i++) {
                float av = (kk == 0) ? a4[i].x :
                           (kk == 1) ? a4[i].y :
                           (kk == 2) ? a4[i].z : a4[i].w;
#pragma unroll
                for (int j = 0; j < 8; j++)
                    acc[i][j] = fmaf(av, bv[j], acc[i][j]);
            }
        }
    }

    float4 bv0 = *(const float4*)(bias + tc * 8);
    float4 bv1 = *(const float4*)(bias + tc * 8 + 4);
    float bb[8] = {bv0.x, bv0.y, bv0.z, bv0.w, bv1.x, bv1.y, bv1.z, bv1.w};

#pragma unroll
    for (int i = 0; i < 8; i++) {
        float* orow = Out + (tr * 8 + i) * outRow + tc * 8;
        float4 o0, o1;
        o0.x = fmaxf(acc[i][0] + bb[0], 0.f);
        o0.y = fmaxf(acc[i][1] + bb[1], 0.f);
        o0.z = fmaxf(acc[i][2] + bb[2], 0.f);
        o0.w = fmaxf(acc[i][3] + bb[3], 0.f);
        o1.x = fmaxf(acc[i][4] + bb[4], 0.f);
        o1.y = fmaxf(acc[i][5] + bb[5], 0.f);
        o1.z = fmaxf(acc[i][6] + bb[6], 0.f);
        o1.w = fmaxf(acc[i][7] + bb[7], 0.f);
        *(float4*)(orow)     = o0;
        *(float4*)(orow + 4) = o1;
    }
}

__global__ void __launch_bounds__(NTHREADS, 1)
topdown_kernel(const float* __restrict__ towers,
               const float* __restrict__ aggregate,
               const float* __restrict__ M1b,
               const float* __restrict__ M2w, const float* __restrict__ M2b,
               const float* __restrict__ M3w, const float* __restrict__ M3b,
               const float* __restrict__ O1b,
               const float* __restrict__ O2w, const float* __restrict__ O2b,
               const float* __restrict__ O3w, const float* __restrict__ O3b,
               float* __restrict__ out)
{
    extern __shared__ float smem[];
    float* X  = smem;                 // TM * XROW  (summary | tower | pad)
    float* H1 = X + TM * XROW;        // TM * NH
    float* H2 = H1 + TM * NH;         // TM * NH
    float* P  = H2 + TM * NH;         // TM running product

    const int tid = threadIdx.x;
    const size_t row0 = (size_t)blockIdx.x * TM;

    // init summary = aggregate (broadcast row), zero the 2 pad cols, P = 1
    for (int i = tid; i < TM * NH; i += NTHREADS) {
        int r = i >> 8, c = i & 255;
        X[r * XROW + c] = aggregate[c];
    }
    for (int i = tid; i < TM * 2; i += NTHREADS) {
        int r = i >> 1, c = 270 + (i & 1);
        X[r * XROW + c] = 0.f;
    }
    if (tid < TM) P[tid] = 1.f;
    __syncthreads();

    for (int s = 0; s < KTOT; s++) {
        // tower slice for this step: towers[:, KTOT-1-s, :]
        for (int i = tid; i < TM * NIN; i += NTHREADS) {
            int r = i / NIN, c = i - r * NIN;
            X[r * XROW + 256 + c] =
                towers[(row0 + r) * (size_t)(KTOT * NIN)
                       + (size_t)(KTOT - 1 - s) * NIN + c];
        }
        __syncthreads();

        // ---- O path first (frees H1/H2 for M path) ----
        gemm_relu_256<XROW>(X,  XROW, g_O1w_pad, O1b, H1, NH, tid);
        __syncthreads();
        gemm_relu_256<NH>(H1, NH, O2w, O2b, H2, NH, tid);
        __syncthreads();

        // O3: logit[r] = H2[r,:] . O3w + O3b; prod *= sigmoid(logit)
        {
            int r = tid >> 2, q = tid & 3;
            const float* h = H2 + r * NH + q * 64;
            const float* w = O3w + q * 64;
            float sum = 0.f;
#pragma unroll
            for (int k = 0; k < 64; k += 4) {
                float4 hv = *(const float4*)(h + k);
                float4 wv = *(const float4*)(w + k);
                sum = fmaf(hv.x, wv.x, sum);
                sum = fmaf(hv.y, wv.y, sum);
                sum = fmaf(hv.z, wv.z, sum);
                sum = fmaf(hv.w, wv.w, sum);
            }
            sum += __shfl_xor_sync(0xffffffffu, sum, 1);
            sum += __shfl_xor_sync(0xffffffffu, sum, 2);
            if (q == 0) {
                float logit = sum + O3b[0];
                P[r] *= 1.f / (1.f + expf(-logit));
            }
        }
        // No sync needed: M1 writes H1 (last read before previous sync),
        // O3 above touches only H2/P.

        // ---- M path ----
        gemm_relu_256<XROW>(X,  XROW, g_M1w_pad, M1b, H1, NH, tid);
        __syncthreads();   // also fences O3's H2 reads before M2 writes H2
        gemm_relu_256<NH>(H1, NH, M2w, M2b, H2, NH, tid);
        __syncthreads();
        // new summary written straight into X[:, 0:256]
        gemm_relu_256<NH>(H2, NH, M3w, M3b, X, XROW, tid);
        __syncthreads();
    }

    if (tid < TM) out[row0 + tid] = P[tid];
}

extern "C" void kernel_launch(void* const* d_in, const int* in_sizes, int n_in,
                              void* d_out, int out_size)
{
    const float* towers    = (const float*)d_in[0];
    const float* aggregate = (const float*)d_in[1];
    const float* M1w = (const float*)d_in[2];
    const float* M1b = (const float*)d_in[3];
    const float* M2w = (const float*)d_in[4];
    const float* M2b = (const float*)d_in[5];
    const float* M3w = (const float*)d_in[6];
    const float* M3b = (const float*)d_in[7];
    const float* O1w = (const float*)d_in[8];
    const float* O1b = (const float*)d_in[9];
    const float* O2w = (const float*)d_in[10];
    const float* O2b = (const float*)d_in[11];
    const float* O3w = (const float*)d_in[12];
    const float* O3b = (const float*)d_in[13];
    float* out = (float*)d_out;

    const int N = in_sizes[0] / (KTOT * NIN);   // 131072

    pad_weights_kernel<<<(XROW * NH + 255) / 256, 256>>>(M1w, O1w);

    const size_t smem_bytes =
        (size_t)(TM * XROW + 2 * TM * NH + TM) * sizeof(float);
    cudaFuncSetAttribute(topdown_kernel,
                         cudaFuncAttributeMaxDynamicSharedMemorySize,
                         (int)smem_bytes);

    topdown_kernel<<<N / TM, NTHREADS, smem_bytes>>>(
        towers, aggregate,
        M1b, M2w, M2b, M3w, M3b,
        O1b, O2w, O2b, O3w, O3b,
        out);
}